// round 14
// baseline (speedup 1.0000x reference)
#include <cuda_runtime.h>
#include <cuda_fp16.h>
#include <cstdint>

#define N_USERS 50000
#define D 128
#define N_EDGES 800000
#define E_PER_WARP 8
#define AS_STRIDE 132          // padded A smem stride in floats (conflict-free)

// -------- device scratch (no cudaMalloc allowed) --------
__device__ __half g_weighted_h[N_USERS * D];   // weighted = emb @ W in fp16
__device__ float2 g_wpack[16 * 16 * 32];       // W pre-packed into MMA B fragments

// ---------------------------------------------------------------------------
// Kernel 0: pack W into B-fragment order, tf32-rounded.
// Wp[(kk*16 + j)*32 + lane] = { W[8kk + c][8j + gid], W[8kk + c + 4][8j + gid] }
// with c = lane&3, gid = lane>>2.  (m16n8k8.row.col B fragment layout.)
// ---------------------------------------------------------------------------
__global__ void pack_w_kernel(const float* __restrict__ W, float2* __restrict__ Wp)
{
    int idx = blockIdx.x * blockDim.x + threadIdx.x;
    if (idx >= 16 * 16 * 32) return;
    int lane = idx & 31;
    int j    = (idx >> 5) & 15;
    int kk   = idx >> 9;
    int c    = lane & 3;
    int gid  = lane >> 2;
    int col  = j * 8 + gid;
    float w0 = W[(kk * 8 + c) * D + col];
    float w1 = W[(kk * 8 + c + 4) * D + col];
    unsigned t0, t1;
    asm("cvt.rna.tf32.f32 %0, %1;" : "=r"(t0) : "f"(w0));
    asm("cvt.rna.tf32.f32 %0, %1;" : "=r"(t1) : "f"(w1));
    Wp[idx] = make_float2(__uint_as_float(t0), __uint_as_float(t1));
}

// ---------------------------------------------------------------------------
// Kernel 1: weighted_h = fp16(user_emb @ W) via tf32 mma.sync; out = user_emb.
// Block = 256 threads (8 warps), 128 rows per block, 2 blocks/SM (66 KB smem).
// A tile staged in smem (tf32-pre-rounded, padded stride).
// B fragments read directly from packed global Wp via __ldg — 64 KB, L1-resident
// and shared across all warps and both co-resident blocks.
// ---------------------------------------------------------------------------
__global__ __launch_bounds__(256) void gemm_kernel(
    const float* __restrict__ emb,
    const float2* __restrict__ Wp,  // packed B fragments (tf32 bits)
    __half* __restrict__ wout,      // [N_USERS, D] fp16
    float* __restrict__ resout)     // [N_USERS, D] fp32 residual init
{
    extern __shared__ float smemf[];
    float* As = smemf;                              // [128 * AS_STRIDE] floats

    const int tid = threadIdx.x;
    const int rowbase = blockIdx.x * 128;

    // ---- stage A tile (tf32-rounded) + fused residual copy out = emb ----
    {
        const float4* src = reinterpret_cast<const float4*>(emb);
        float4* dst = reinterpret_cast<float4*>(resout);
        float4* As4 = reinterpret_cast<float4*>(As);
        #pragma unroll
        for (int i = 0; i < 16; i++) {              // 128 rows * 32 float4
            int idx = i * 256 + tid;
            int r = idx >> 5;                       // tile row
            int q = idx & 31;                       // float4 within row
            int gr = min(rowbase + r, N_USERS - 1);
            float4 v = src[(size_t)gr * 32 + q];
            if (rowbase + r < N_USERS)
                dst[(size_t)(rowbase + r) * 32 + q] = v;   // exact residual
            float4 t;
            asm("cvt.rna.tf32.f32 %0, %1;" : "=f"(t.x) : "f"(v.x));
            asm("cvt.rna.tf32.f32 %0, %1;" : "=f"(t.y) : "f"(v.y));
            asm("cvt.rna.tf32.f32 %0, %1;" : "=f"(t.z) : "f"(v.z));
            asm("cvt.rna.tf32.f32 %0, %1;" : "=f"(t.w) : "f"(v.w));
            As4[r * (AS_STRIDE / 4) + q] = t;       // stride 33 float4
        }
    }
    __syncthreads();

    const int warp = tid >> 5;
    const int lane = tid & 31;
    const int gid  = lane >> 2;     // 0..7
    const int c    = lane & 3;      // 0..3

    const int trA = warp * 16 + gid;        // tile rows
    const int trB = warp * 16 + gid + 8;
    const int rA = rowbase + trA;
    const int rB = rowbase + trB;
    const float* pA = As + trA * AS_STRIDE;
    const float* pB = As + trB * AS_STRIDE;

    float acc[16][4];
    #pragma unroll
    for (int j = 0; j < 16; j++)
        #pragma unroll
        for (int q = 0; q < 4; q++) acc[j][q] = 0.f;

    #pragma unroll 1
    for (int kk = 0; kk < 16; kk++) {
        const int k0 = kk * 8;
        // A fragment, pre-rounded (conflict-free: bank = (4*gid+c+8kk)%32)
        unsigned a0 = __float_as_uint(pA[k0 + c]);
        unsigned a1 = __float_as_uint(pB[k0 + c]);
        unsigned a2 = __float_as_uint(pA[k0 + c + 4]);
        unsigned a3 = __float_as_uint(pB[k0 + c + 4]);

        const float2* wrow = Wp + kk * 16 * 32 + lane;
        #pragma unroll
        for (int j = 0; j < 16; j++) {
            float2 bp = __ldg(wrow + j * 32);       // warp-coalesced LDG.64, L1-hot
            unsigned b0 = __float_as_uint(bp.x);
            unsigned b1 = __float_as_uint(bp.y);
            asm volatile(
                "mma.sync.aligned.m16n8k8.row.col.f32.tf32.tf32.f32 "
                "{%0,%1,%2,%3}, {%4,%5,%6,%7}, {%8,%9}, {%0,%1,%2,%3};"
                : "+f"(acc[j][0]), "+f"(acc[j][1]), "+f"(acc[j][2]), "+f"(acc[j][3])
                : "r"(a0), "r"(a1), "r"(a2), "r"(a3), "r"(b0), "r"(b1));
        }
    }

    // ---- epilogue: fp16 weighted ----
    #pragma unroll
    for (int j = 0; j < 16; j++) {
        const int col = j * 8 + 2 * c;
        __half2 hA = __floats2half2_rn(acc[j][0], acc[j][1]);
        __half2 hB = __floats2half2_rn(acc[j][2], acc[j][3]);
        if (rA < N_USERS) *reinterpret_cast<__half2*>(wout + (size_t)rA * D + col) = hA;
        if (rB < N_USERS) *reinterpret_cast<__half2*>(wout + (size_t)rB * D + col) = hB;
    }
}

// ---------------------------------------------------------------------------
// Kernel 2: out[rows[e]] += vals[e] * weighted_h[cols[e]]
// 8 edges per warp: lanes 0-7 hold metadata, 8 gathers in flight, 8 REDs.
// 800000 = 100000 warps * 8 exactly; no tail.
// ---------------------------------------------------------------------------
__global__ __launch_bounds__(256) void edge_kernel(
    const int* __restrict__ rows,
    const int* __restrict__ cols,
    const float* __restrict__ vals,
    const __half* __restrict__ weighted,
    float* __restrict__ out)
{
    const int warp = (blockIdx.x * blockDim.x + threadIdx.x) >> 5;
    const int lane = threadIdx.x & 31;
    const long long e0 = (long long)warp * E_PER_WARP;
    if (e0 >= N_EDGES) return;

    const int eidx = (int)e0 + (lane & (E_PER_WARP - 1));
    int   ri = __ldg(rows + eidx);
    int   ci = __ldg(cols + eidx);
    float vi = __ldg(vals + eidx);

    uint2 pk[E_PER_WARP];
    #pragma unroll
    for (int i = 0; i < E_PER_WARP; i++) {
        int cc = __shfl_sync(0xffffffffu, ci, i);
        pk[i] = *reinterpret_cast<const uint2*>(weighted + (size_t)cc * D + lane * 4);
    }

    #pragma unroll
    for (int i = 0; i < E_PER_WARP; i++) {
        int   r = __shfl_sync(0xffffffffu, ri, i);
        float v = __shfl_sync(0xffffffffu, vi, i);
        __half2 h0 = *reinterpret_cast<__half2*>(&pk[i].x);
        __half2 h1 = *reinterpret_cast<__half2*>(&pk[i].y);
        float2 f0 = __half22float2(h0);
        float2 f1 = __half22float2(h1);
        float px = v * f0.x, py = v * f0.y, pz = v * f1.x, pw = v * f1.y;
        float* dst = out + (size_t)r * D + lane * 4;
        asm volatile("red.global.add.v4.f32 [%0], {%1,%2,%3,%4};"
                     :: "l"(dst), "f"(px), "f"(py), "f"(pz), "f"(pw)
                     : "memory");
    }
}

// ---------------------------------------------------------------------------
// Launch
// ---------------------------------------------------------------------------
extern "C" void kernel_launch(void* const* d_in, const int* in_sizes, int n_in,
                              void* d_out, int out_size)
{
    const float* user_emb = (const float*)d_in[0];
    const float* social_w = (const float*)d_in[1];
    const int*   rows     = (const int*)d_in[2];
    const int*   cols     = (const int*)d_in[3];
    const float* vals     = (const float*)d_in[4];
    float*       out      = (float*)d_out;

    __half* weighted;  cudaGetSymbolAddress((void**)&weighted, g_weighted_h);
    float2* wpack;     cudaGetSymbolAddress((void**)&wpack,    g_wpack);

    // 0. pack W into B-fragment order (tiny)
    pack_w_kernel<<<32, 256>>>(social_w, wpack);

    // 1. GEMM (tf32 tensor cores), B fragments streamed from L1-resident Wp
    {
        const int smem_bytes = 128 * AS_STRIDE * sizeof(float);   // 67584 -> 2 blk/SM
        cudaFuncSetAttribute(gemm_kernel,
                             cudaFuncAttributeMaxDynamicSharedMemorySize, smem_bytes);
        int nblk = (N_USERS + 127) / 128;                         // 391
        gemm_kernel<<<nblk, 256, smem_bytes>>>(user_emb, wpack, weighted, out);
    }

    // 2. scatter-add edges, 8 edges per warp
    {
        int nwarps = N_EDGES / E_PER_WARP;              // 100000
        int nblk = (nwarps * 32 + 255) / 256;           // 12500
        edge_kernel<<<nblk, 256>>>(rows, cols, vals, weighted, out);
    }
}

// round 15
// speedup vs baseline: 1.0125x; 1.0125x over previous
#include <cuda_runtime.h>
#include <cuda_fp16.h>
#include <cstdint>

#define N_USERS 50000
#define D 128
#define N_EDGES 800000
#define E_PER_WARP 8
#define AS_STRIDE 132          // padded A smem stride in floats (conflict-free)

// -------- device scratch (no cudaMalloc allowed) --------
__device__ __half g_weighted_h[N_USERS * D];   // weighted = emb @ W in fp16
__device__ float2 g_wpack[16 * 16 * 32];       // W pre-packed into MMA B fragments

// ---------------------------------------------------------------------------
// Kernel 0: pack W into B-fragment order, tf32-rounded.
// Wp[(kk*16 + j)*32 + lane] = { W[8kk + c][8j + gid], W[8kk + c + 4][8j + gid] }
// with c = lane&3, gid = lane>>2.  (m16n8k8.row.col B fragment layout.)
// ---------------------------------------------------------------------------
__global__ void pack_w_kernel(const float* __restrict__ W, float2* __restrict__ Wp)
{
    int idx = blockIdx.x * blockDim.x + threadIdx.x;
    if (idx >= 16 * 16 * 32) return;
    int lane = idx & 31;
    int j    = (idx >> 5) & 15;
    int kk   = idx >> 9;
    int c    = lane & 3;
    int gid  = lane >> 2;
    int col  = j * 8 + gid;
    float w0 = W[(kk * 8 + c) * D + col];
    float w1 = W[(kk * 8 + c + 4) * D + col];
    unsigned t0, t1;
    asm("cvt.rna.tf32.f32 %0, %1;" : "=r"(t0) : "f"(w0));
    asm("cvt.rna.tf32.f32 %0, %1;" : "=r"(t1) : "f"(w1));
    Wp[idx] = make_float2(__uint_as_float(t0), __uint_as_float(t1));
}

// ---------------------------------------------------------------------------
// Kernel 1: weighted_h = fp16(user_emb @ W) via tf32 mma.sync; out = user_emb.
// Block = 512 threads (16 warps), 128 rows per block (same block count and
// staging traffic as the 256-thread version — just 2x warps to hide latency).
// Warp w: row-group w>>1 (16 rows), j-half w&1 (64 of 128 cols).
// ---------------------------------------------------------------------------
__global__ __launch_bounds__(512) void gemm_kernel(
    const float* __restrict__ emb,
    const float2* __restrict__ Wp,  // packed B fragments (tf32 bits)
    __half* __restrict__ wout,      // [N_USERS, D] fp16
    float* __restrict__ resout)     // [N_USERS, D] fp32 residual init
{
    extern __shared__ float smemf[];
    float*  As  = smemf;                            // [128 * AS_STRIDE] floats
    float2* Wps = reinterpret_cast<float2*>(smemf + 128 * AS_STRIDE);  // [8192]

    const int tid = threadIdx.x;
    const int rowbase = blockIdx.x * 128;

    // ---- stage A tile (coalesced float4) + fused residual copy out = emb ----
    {
        const float4* src = reinterpret_cast<const float4*>(emb);
        float4* dst = reinterpret_cast<float4*>(resout);
        float4* As4 = reinterpret_cast<float4*>(As);
        #pragma unroll
        for (int i = 0; i < 8; i++) {               // 128 rows * 32 float4 = 4096
            int idx = i * 512 + tid;
            int r = idx >> 5;                       // tile row
            int q = idx & 31;                       // float4 within row
            int gr = min(rowbase + r, N_USERS - 1);
            float4 v = src[(size_t)gr * 32 + q];
            As4[r * (AS_STRIDE / 4) + q] = v;       // stride 33 float4
            if (rowbase + r < N_USERS)
                dst[(size_t)(rowbase + r) * 32 + q] = v;
        }
    }

    // ---- stage packed W fragments (coalesced float4 over float2 pairs) ----
    {
        const float4* srcp = reinterpret_cast<const float4*>(Wp);
        float4* dstp = reinterpret_cast<float4*>(Wps);
        #pragma unroll
        for (int i = 0; i < 8; i++)                 // 4096 float4
            dstp[i * 512 + tid] = srcp[i * 512 + tid];
    }
    __syncthreads();

    const int warp   = tid >> 5;    // 0..15
    const int lane   = tid & 31;
    const int gid    = lane >> 2;   // 0..7
    const int c      = lane & 3;    // 0..3
    const int rowgrp = warp >> 1;   // 0..7
    const int jhalf  = warp & 1;    // 0..1

    const int trA = rowgrp * 16 + gid;      // tile rows
    const int trB = rowgrp * 16 + gid + 8;
    const int rA = rowbase + trA;
    const int rB = rowbase + trB;
    const float* pA = As + trA * AS_STRIDE;
    const float* pB = As + trB * AS_STRIDE;

    float acc[8][4];
    #pragma unroll
    for (int j = 0; j < 8; j++)
        #pragma unroll
        for (int q = 0; q < 4; q++) acc[j][q] = 0.f;

    #pragma unroll 1
    for (int kk = 0; kk < 16; kk++) {
        const int k0 = kk * 8;
        // A fragment (conflict-free: bank = (4*gid + c + 8kk) % 32, all distinct)
        float a0f = pA[k0 + c];
        float a1f = pB[k0 + c];
        float a2f = pA[k0 + c + 4];
        float a3f = pB[k0 + c + 4];
        unsigned a0, a1, a2, a3;
        asm("cvt.rna.tf32.f32 %0, %1;" : "=r"(a0) : "f"(a0f));
        asm("cvt.rna.tf32.f32 %0, %1;" : "=r"(a1) : "f"(a1f));
        asm("cvt.rna.tf32.f32 %0, %1;" : "=r"(a2) : "f"(a2f));
        asm("cvt.rna.tf32.f32 %0, %1;" : "=r"(a3) : "f"(a3f));

        const float2* wrow = Wps + (kk * 16 + jhalf * 8) * 32 + lane;
        #pragma unroll
        for (int j = 0; j < 8; j++) {
            float2 bp = wrow[j * 32];               // one LDS.64, conflict-free
            unsigned b0 = __float_as_uint(bp.x);
            unsigned b1 = __float_as_uint(bp.y);
            asm volatile(
                "mma.sync.aligned.m16n8k8.row.col.f32.tf32.tf32.f32 "
                "{%0,%1,%2,%3}, {%4,%5,%6,%7}, {%8,%9}, {%0,%1,%2,%3};"
                : "+f"(acc[j][0]), "+f"(acc[j][1]), "+f"(acc[j][2]), "+f"(acc[j][3])
                : "r"(a0), "r"(a1), "r"(a2), "r"(a3), "r"(b0), "r"(b1));
        }
    }

    // ---- epilogue: fp16 weighted ----
    #pragma unroll
    for (int j = 0; j < 8; j++) {
        const int col = (jhalf * 8 + j) * 8 + 2 * c;
        __half2 hA = __floats2half2_rn(acc[j][0], acc[j][1]);
        __half2 hB = __floats2half2_rn(acc[j][2], acc[j][3]);
        if (rA < N_USERS) *reinterpret_cast<__half2*>(wout + (size_t)rA * D + col) = hA;
        if (rB < N_USERS) *reinterpret_cast<__half2*>(wout + (size_t)rB * D + col) = hB;
    }
}

// ---------------------------------------------------------------------------
// Kernel 2: out[rows[e]] += vals[e] * weighted_h[cols[e]]
// 8 edges per warp: lanes 0-7 hold metadata, 8 gathers in flight, 8 REDs.
// 800000 = 100000 warps * 8 exactly; no tail.
// ---------------------------------------------------------------------------
__global__ __launch_bounds__(256) void edge_kernel(
    const int* __restrict__ rows,
    const int* __restrict__ cols,
    const float* __restrict__ vals,
    const __half* __restrict__ weighted,
    float* __restrict__ out)
{
    const int warp = (blockIdx.x * blockDim.x + threadIdx.x) >> 5;
    const int lane = threadIdx.x & 31;
    const long long e0 = (long long)warp * E_PER_WARP;
    if (e0 >= N_EDGES) return;

    const int eidx = (int)e0 + (lane & (E_PER_WARP - 1));
    int   ri = __ldg(rows + eidx);
    int   ci = __ldg(cols + eidx);
    float vi = __ldg(vals + eidx);

    uint2 pk[E_PER_WARP];
    #pragma unroll
    for (int i = 0; i < E_PER_WARP; i++) {
        int cc = __shfl_sync(0xffffffffu, ci, i);
        pk[i] = *reinterpret_cast<const uint2*>(weighted + (size_t)cc * D + lane * 4);
    }

    #pragma unroll
    for (int i = 0; i < E_PER_WARP; i++) {
        int   r = __shfl_sync(0xffffffffu, ri, i);
        float v = __shfl_sync(0xffffffffu, vi, i);
        __half2 h0 = *reinterpret_cast<__half2*>(&pk[i].x);
        __half2 h1 = *reinterpret_cast<__half2*>(&pk[i].y);
        float2 f0 = __half22float2(h0);
        float2 f1 = __half22float2(h1);
        float px = v * f0.x, py = v * f0.y, pz = v * f1.x, pw = v * f1.y;
        float* dst = out + (size_t)r * D + lane * 4;
        asm volatile("red.global.add.v4.f32 [%0], {%1,%2,%3,%4};"
                     :: "l"(dst), "f"(px), "f"(py), "f"(pz), "f"(pw)
                     : "memory");
    }
}

// ---------------------------------------------------------------------------
// Launch
// ---------------------------------------------------------------------------
extern "C" void kernel_launch(void* const* d_in, const int* in_sizes, int n_in,
                              void* d_out, int out_size)
{
    const float* user_emb = (const float*)d_in[0];
    const float* social_w = (const float*)d_in[1];
    const int*   rows     = (const int*)d_in[2];
    const int*   cols     = (const int*)d_in[3];
    const float* vals     = (const float*)d_in[4];
    float*       out      = (float*)d_out;

    __half* weighted;  cudaGetSymbolAddress((void**)&weighted, g_weighted_h);
    float2* wpack;     cudaGetSymbolAddress((void**)&wpack,    g_wpack);

    // 0. pack W into B-fragment order (tiny)
    pack_w_kernel<<<32, 256>>>(social_w, wpack);

    // 1. GEMM (tf32 tensor cores) + fused residual init, 512 threads/block
    {
        const int smem_bytes = 128 * AS_STRIDE * sizeof(float)
                             + 16 * 16 * 32 * sizeof(float2);   // 67584 + 65536
        cudaFuncSetAttribute(gemm_kernel,
                             cudaFuncAttributeMaxDynamicSharedMemorySize, smem_bytes);
        int nblk = (N_USERS + 127) / 128;                       // 391
        gemm_kernel<<<nblk, 512, smem_bytes>>>(user_emb, wpack, weighted, out);
    }

    // 2. scatter-add edges, 8 edges per warp
    {
        int nwarps = N_EDGES / E_PER_WARP;              // 100000
        int nblk = (nwarps * 32 + 255) / 256;           // 12500
        edge_kernel<<<nblk, 256>>>(rows, cols, vals, weighted, out);
    }
}

// round 16
// speedup vs baseline: 1.0228x; 1.0101x over previous
#include <cuda_runtime.h>
#include <cuda_fp16.h>
#include <cstdint>

#define N_USERS 50000
#define D 128
#define N_EDGES 800000
#define E_PER_WARP 8
#define AS_STRIDE 132          // padded A smem stride in floats (conflict-free)

// -------- device scratch (no cudaMalloc allowed) --------
__device__ __half g_weighted_h[N_USERS * D];   // weighted = emb @ W in fp16
__device__ float2 g_wpack[16 * 16 * 32];       // W pre-packed into MMA B fragments

// ---------------------------------------------------------------------------
// Kernel 0: pack W into B-fragment order, tf32-rounded.
// Wp[(kk*16 + j)*32 + lane] = { W[8kk + c][8j + gid], W[8kk + c + 4][8j + gid] }
// with c = lane&3, gid = lane>>2.  (m16n8k8.row.col B fragment layout.)
// ---------------------------------------------------------------------------
__global__ void pack_w_kernel(const float* __restrict__ W, float2* __restrict__ Wp)
{
    int idx = blockIdx.x * blockDim.x + threadIdx.x;
    if (idx < 16 * 16 * 32) {
        int lane = idx & 31;
        int j    = (idx >> 5) & 15;
        int kk   = idx >> 9;
        int c    = lane & 3;
        int gid  = lane >> 2;
        int col  = j * 8 + gid;
        float w0 = W[(kk * 8 + c) * D + col];
        float w1 = W[(kk * 8 + c + 4) * D + col];
        unsigned t0, t1;
        asm("cvt.rna.tf32.f32 %0, %1;" : "=r"(t0) : "f"(w0));
        asm("cvt.rna.tf32.f32 %0, %1;" : "=r"(t1) : "f"(w1));
        Wp[idx] = make_float2(__uint_as_float(t0), __uint_as_float(t1));
    }
}

// ---------------------------------------------------------------------------
// Kernel 1: weighted_h = fp16(user_emb @ W) via tf32 mma.sync; out = user_emb.
// Launched with PDL: blocks start while pack_w still runs; the A-tile staging
// (independent of Wp) overlaps pack; cudaGridDependencySynchronize() gates the
// Wps staging. Block = 256 threads (8 warps), 128 rows per block.
// ---------------------------------------------------------------------------
__global__ __launch_bounds__(256) void gemm_kernel(
    const float* __restrict__ emb,
    const float2* __restrict__ Wp,  // packed B fragments (tf32 bits)
    __half* __restrict__ wout,      // [N_USERS, D] fp16
    float* __restrict__ resout)     // [N_USERS, D] fp32 residual init
{
    extern __shared__ float smemf[];
    float*  As  = smemf;                            // [128 * AS_STRIDE] floats
    float2* Wps = reinterpret_cast<float2*>(smemf + 128 * AS_STRIDE);  // [8192]

    const int tid = threadIdx.x;
    const int rowbase = blockIdx.x * 128;

    // ---- stage A tile (coalesced float4) + fused residual copy out = emb ----
    // Runs BEFORE the grid-dependency sync: overlaps with pack_w.
    {
        const float4* src = reinterpret_cast<const float4*>(emb);
        float4* dst = reinterpret_cast<float4*>(resout);
        float4* As4 = reinterpret_cast<float4*>(As);
        #pragma unroll
        for (int i = 0; i < 16; i++) {              // 128 rows * 32 float4
            int idx = i * 256 + tid;
            int r = idx >> 5;                       // tile row
            int q = idx & 31;                       // float4 within row
            int gr = min(rowbase + r, N_USERS - 1);
            float4 v = src[(size_t)gr * 32 + q];
            As4[r * (AS_STRIDE / 4) + q] = v;       // stride 33 float4
            if (rowbase + r < N_USERS)
                dst[(size_t)(rowbase + r) * 32 + q] = v;
        }
    }

    // ---- wait for pack_w's Wp to be complete and visible ----
    cudaGridDependencySynchronize();

    // ---- stage packed W fragments (coalesced float4 over float2 pairs) ----
    {
        const float4* srcp = reinterpret_cast<const float4*>(Wp);
        float4* dstp = reinterpret_cast<float4*>(Wps);
        #pragma unroll
        for (int i = 0; i < 16; i++)                // 4096 float4
            dstp[i * 256 + tid] = srcp[i * 256 + tid];
    }
    __syncthreads();

    const int warp = tid >> 5;
    const int lane = tid & 31;
    const int gid  = lane >> 2;     // 0..7
    const int c    = lane & 3;      // 0..3

    const int trA = warp * 16 + gid;        // tile rows
    const int trB = warp * 16 + gid + 8;
    const int rA = rowbase + trA;
    const int rB = rowbase + trB;
    const float* pA = As + trA * AS_STRIDE;
    const float* pB = As + trB * AS_STRIDE;

    float acc[16][4];
    #pragma unroll
    for (int j = 0; j < 16; j++)
        #pragma unroll
        for (int q = 0; q < 4; q++) acc[j][q] = 0.f;

    #pragma unroll 1
    for (int kk = 0; kk < 16; kk++) {
        const int k0 = kk * 8;
        // A fragment (conflict-free: bank = (4*gid + c + 8kk) % 32, all distinct)
        float a0f = pA[k0 + c];
        float a1f = pB[k0 + c];
        float a2f = pA[k0 + c + 4];
        float a3f = pB[k0 + c + 4];
        unsigned a0, a1, a2, a3;
        asm("cvt.rna.tf32.f32 %0, %1;" : "=r"(a0) : "f"(a0f));
        asm("cvt.rna.tf32.f32 %0, %1;" : "=r"(a1) : "f"(a1f));
        asm("cvt.rna.tf32.f32 %0, %1;" : "=r"(a2) : "f"(a2f));
        asm("cvt.rna.tf32.f32 %0, %1;" : "=r"(a3) : "f"(a3f));

        const float2* wrow = Wps + kk * 16 * 32 + lane;
        #pragma unroll
        for (int j = 0; j < 16; j++) {
            float2 bp = wrow[j * 32];               // one LDS.64, conflict-free
            unsigned b0 = __float_as_uint(bp.x);
            unsigned b1 = __float_as_uint(bp.y);
            asm volatile(
                "mma.sync.aligned.m16n8k8.row.col.f32.tf32.tf32.f32 "
                "{%0,%1,%2,%3}, {%4,%5,%6,%7}, {%8,%9}, {%0,%1,%2,%3};"
                : "+f"(acc[j][0]), "+f"(acc[j][1]), "+f"(acc[j][2]), "+f"(acc[j][3])
                : "r"(a0), "r"(a1), "r"(a2), "r"(a3), "r"(b0), "r"(b1));
        }
    }

    // ---- epilogue: fp16 weighted ----
    #pragma unroll
    for (int j = 0; j < 16; j++) {
        const int col = j * 8 + 2 * c;
        __half2 hA = __floats2half2_rn(acc[j][0], acc[j][1]);
        __half2 hB = __floats2half2_rn(acc[j][2], acc[j][3]);
        if (rA < N_USERS) *reinterpret_cast<__half2*>(wout + (size_t)rA * D + col) = hA;
        if (rB < N_USERS) *reinterpret_cast<__half2*>(wout + (size_t)rB * D + col) = hB;
    }
}

// ---------------------------------------------------------------------------
// Kernel 2: out[rows[e]] += vals[e] * weighted_h[cols[e]]
// Launched with PDL: metadata loads overlap gemm's tail; the grid-dependency
// sync gates the gathers/REDs. 8 edges per warp, MLP=8. 800000 = 100000*8.
// ---------------------------------------------------------------------------
__global__ __launch_bounds__(256) void edge_kernel(
    const int* __restrict__ rows,
    const int* __restrict__ cols,
    const float* __restrict__ vals,
    const __half* __restrict__ weighted,
    float* __restrict__ out)
{
    const int warp = (blockIdx.x * blockDim.x + threadIdx.x) >> 5;
    const int lane = threadIdx.x & 31;
    const long long e0 = (long long)warp * E_PER_WARP;

    int   ri = 0, ci = 0;
    float vi = 0.f;
    if (e0 < N_EDGES) {
        const int eidx = (int)e0 + (lane & (E_PER_WARP - 1));
        ri = __ldg(rows + eidx);        // metadata: not written by gemm
        ci = __ldg(cols + eidx);
        vi = __ldg(vals + eidx);
    }

    // wait for gemm's weighted + residual-out writes to be visible
    cudaGridDependencySynchronize();

    if (e0 >= N_EDGES) return;

    uint2 pk[E_PER_WARP];
    #pragma unroll
    for (int i = 0; i < E_PER_WARP; i++) {
        int cc = __shfl_sync(0xffffffffu, ci, i);
        pk[i] = *reinterpret_cast<const uint2*>(weighted + (size_t)cc * D + lane * 4);
    }

    #pragma unroll
    for (int i = 0; i < E_PER_WARP; i++) {
        int   r = __shfl_sync(0xffffffffu, ri, i);
        float v = __shfl_sync(0xffffffffu, vi, i);
        __half2 h0 = *reinterpret_cast<__half2*>(&pk[i].x);
        __half2 h1 = *reinterpret_cast<__half2*>(&pk[i].y);
        float2 f0 = __half22float2(h0);
        float2 f1 = __half22float2(h1);
        float px = v * f0.x, py = v * f0.y, pz = v * f1.x, pw = v * f1.y;
        float* dst = out + (size_t)r * D + lane * 4;
        asm volatile("red.global.add.v4.f32 [%0], {%1,%2,%3,%4};"
                     :: "l"(dst), "f"(px), "f"(py), "f"(pz), "f"(pw)
                     : "memory");
    }
}

// ---------------------------------------------------------------------------
// Launch — pack, then PDL-overlapped gemm, then PDL-overlapped edge.
// ---------------------------------------------------------------------------
extern "C" void kernel_launch(void* const* d_in, const int* in_sizes, int n_in,
                              void* d_out, int out_size)
{
    const float* user_emb = (const float*)d_in[0];
    const float* social_w = (const float*)d_in[1];
    const int*   rows     = (const int*)d_in[2];
    const int*   cols     = (const int*)d_in[3];
    const float* vals     = (const float*)d_in[4];
    float*       out      = (float*)d_out;

    __half* weighted;  cudaGetSymbolAddress((void**)&weighted, g_weighted_h);
    float2* wpack;     cudaGetSymbolAddress((void**)&wpack,    g_wpack);

    // 0. pack W into B-fragment order (tiny; hidden under gemm's A-staging)
    pack_w_kernel<<<32, 256>>>(social_w, wpack);

    cudaLaunchAttribute pdl[1];
    pdl[0].id = cudaLaunchAttributeProgrammaticStreamSerialization;
    pdl[0].val.programmaticStreamSerializationAllowed = 1;

    // 1. GEMM (tf32 tensor cores) + fused residual init — PDL over pack
    {
        const int smem_bytes = 128 * AS_STRIDE * sizeof(float)
                             + 16 * 16 * 32 * sizeof(float2);   // 67584 + 65536
        cudaFuncSetAttribute(gemm_kernel,
                             cudaFuncAttributeMaxDynamicSharedMemorySize, smem_bytes);
        cudaLaunchConfig_t cfg = {};
        cfg.gridDim = dim3((N_USERS + 127) / 128);              // 391
        cfg.blockDim = dim3(256);
        cfg.dynamicSmemBytes = smem_bytes;
        cfg.stream = 0;
        cfg.attrs = pdl;
        cfg.numAttrs = 1;
        cudaLaunchKernelEx(&cfg, gemm_kernel, user_emb, wpack, weighted, out);
    }

    // 2. scatter-add edges — PDL over gemm
    {
        int nwarps = N_EDGES / E_PER_WARP;              // 100000
        cudaLaunchConfig_t cfg = {};
        cfg.gridDim = dim3((nwarps * 32 + 255) / 256);  // 12500
        cfg.blockDim = dim3(256);
        cfg.dynamicSmemBytes = 0;
        cfg.stream = 0;
        cfg.attrs = pdl;
        cfg.numAttrs = 1;
        cudaLaunchKernelEx(&cfg, edge_kernel, rows, cols, vals,
                           (const __half*)weighted, out);
    }
}

// round 17
// speedup vs baseline: 1.0462x; 1.0229x over previous
#include <cuda_runtime.h>
#include <cuda_fp16.h>
#include <cstdint>

#define N_USERS 50000
#define D 128
#define N_EDGES 800000
#define E_PER_WARP 8
#define AS_STRIDE 132          // padded A smem stride in floats (conflict-free)

// -------- device scratch (no cudaMalloc allowed) --------
__device__ __half g_weighted_h[N_USERS * D];   // weighted = emb @ W in fp16
__device__ float2 g_wpack[16 * 16 * 32];       // W pre-packed into MMA B fragments

// ---------------------------------------------------------------------------
// Kernel 0: pack W into B-fragment order, tf32-rounded.
// Wp[(kk*16 + j)*32 + lane] = { W[8kk + c][8j + gid], W[8kk + c + 4][8j + gid] }
// with c = lane&3, gid = lane>>2.  (m16n8k8.row.col B fragment layout.)
// Triggers programmatic launch completion so the PDL'd gemm can start its
// Wp-independent staging while pack drains.
// ---------------------------------------------------------------------------
__global__ void pack_w_kernel(const float* __restrict__ W, float2* __restrict__ Wp)
{
    int idx = blockIdx.x * blockDim.x + threadIdx.x;
    if (idx < 16 * 16 * 32) {
        int lane = idx & 31;
        int j    = (idx >> 5) & 15;
        int kk   = idx >> 9;
        int c    = lane & 3;
        int gid  = lane >> 2;
        int col  = j * 8 + gid;
        float w0 = W[(kk * 8 + c) * D + col];
        float w1 = W[(kk * 8 + c + 4) * D + col];
        unsigned t0, t1;
        asm("cvt.rna.tf32.f32 %0, %1;" : "=r"(t0) : "f"(w0));
        asm("cvt.rna.tf32.f32 %0, %1;" : "=r"(t1) : "f"(w1));
        Wp[idx] = make_float2(__uint_as_float(t0), __uint_as_float(t1));
    }
    cudaTriggerProgrammaticLaunchCompletion();
}

// ---------------------------------------------------------------------------
// Kernel 1: weighted_h = fp16(user_emb @ W) via tf32 mma.sync; out = user_emb.
// PDL: blocks start while pack_w drains; A-tile staging (independent of Wp)
// overlaps pack; cudaGridDependencySynchronize() gates the Wps staging.
// Block = 256 threads (8 warps), 128 rows per block.
// ---------------------------------------------------------------------------
__global__ __launch_bounds__(256) void gemm_kernel(
    const float* __restrict__ emb,
    const float2* __restrict__ Wp,  // packed B fragments (tf32 bits)
    __half* __restrict__ wout,      // [N_USERS, D] fp16
    float* __restrict__ resout)     // [N_USERS, D] fp32 residual init
{
    extern __shared__ float smemf[];
    float*  As  = smemf;                            // [128 * AS_STRIDE] floats
    float2* Wps = reinterpret_cast<float2*>(smemf + 128 * AS_STRIDE);  // [8192]

    const int tid = threadIdx.x;
    const int rowbase = blockIdx.x * 128;

    // ---- stage A tile (coalesced float4) + fused residual copy out = emb ----
    // Runs BEFORE the grid-dependency sync: overlaps with pack_w's tail.
    {
        const float4* src = reinterpret_cast<const float4*>(emb);
        float4* dst = reinterpret_cast<float4*>(resout);
        float4* As4 = reinterpret_cast<float4*>(As);
        #pragma unroll
        for (int i = 0; i < 16; i++) {              // 128 rows * 32 float4
            int idx = i * 256 + tid;
            int r = idx >> 5;                       // tile row
            int q = idx & 31;                       // float4 within row
            int gr = min(rowbase + r, N_USERS - 1);
            float4 v = src[(size_t)gr * 32 + q];
            As4[r * (AS_STRIDE / 4) + q] = v;       // stride 33 float4
            if (rowbase + r < N_USERS)
                dst[(size_t)(rowbase + r) * 32 + q] = v;
        }
    }

    // ---- wait for pack_w's Wp to be complete and visible ----
    cudaGridDependencySynchronize();

    // ---- stage packed W fragments (coalesced float4 over float2 pairs) ----
    {
        const float4* srcp = reinterpret_cast<const float4*>(Wp);
        float4* dstp = reinterpret_cast<float4*>(Wps);
        #pragma unroll
        for (int i = 0; i < 16; i++)                // 4096 float4
            dstp[i * 256 + tid] = srcp[i * 256 + tid];
    }
    __syncthreads();

    const int warp = tid >> 5;
    const int lane = tid & 31;
    const int gid  = lane >> 2;     // 0..7
    const int c    = lane & 3;      // 0..3

    const int trA = warp * 16 + gid;        // tile rows
    const int trB = warp * 16 + gid + 8;
    const int rA = rowbase + trA;
    const int rB = rowbase + trB;
    const float* pA = As + trA * AS_STRIDE;
    const float* pB = As + trB * AS_STRIDE;

    float acc[16][4];
    #pragma unroll
    for (int j = 0; j < 16; j++)
        #pragma unroll
        for (int q = 0; q < 4; q++) acc[j][q] = 0.f;

    #pragma unroll 1
    for (int kk = 0; kk < 16; kk++) {
        const int k0 = kk * 8;
        // A fragment (conflict-free: bank = (4*gid + c + 8kk) % 32, all distinct)
        float a0f = pA[k0 + c];
        float a1f = pB[k0 + c];
        float a2f = pA[k0 + c + 4];
        float a3f = pB[k0 + c + 4];
        unsigned a0, a1, a2, a3;
        asm("cvt.rna.tf32.f32 %0, %1;" : "=r"(a0) : "f"(a0f));
        asm("cvt.rna.tf32.f32 %0, %1;" : "=r"(a1) : "f"(a1f));
        asm("cvt.rna.tf32.f32 %0, %1;" : "=r"(a2) : "f"(a2f));
        asm("cvt.rna.tf32.f32 %0, %1;" : "=r"(a3) : "f"(a3f));

        const float2* wrow = Wps + kk * 16 * 32 + lane;
        #pragma unroll
        for (int j = 0; j < 16; j++) {
            float2 bp = wrow[j * 32];               // one LDS.64, conflict-free
            unsigned b0 = __float_as_uint(bp.x);
            unsigned b1 = __float_as_uint(bp.y);
            asm volatile(
                "mma.sync.aligned.m16n8k8.row.col.f32.tf32.tf32.f32 "
                "{%0,%1,%2,%3}, {%4,%5,%6,%7}, {%8,%9}, {%0,%1,%2,%3};"
                : "+f"(acc[j][0]), "+f"(acc[j][1]), "+f"(acc[j][2]), "+f"(acc[j][3])
                : "r"(a0), "r"(a1), "r"(a2), "r"(a3), "r"(b0), "r"(b1));
        }
    }

    // ---- epilogue: fp16 weighted ----
    #pragma unroll
    for (int j = 0; j < 16; j++) {
        const int col = j * 8 + 2 * c;
        __half2 hA = __floats2half2_rn(acc[j][0], acc[j][1]);
        __half2 hB = __floats2half2_rn(acc[j][2], acc[j][3]);
        if (rA < N_USERS) *reinterpret_cast<__half2*>(wout + (size_t)rA * D + col) = hA;
        if (rB < N_USERS) *reinterpret_cast<__half2*>(wout + (size_t)rB * D + col) = hB;
    }

    // allow the PDL'd edge kernel to be scheduled into our tail wave
    cudaTriggerProgrammaticLaunchCompletion();
}

// ---------------------------------------------------------------------------
// Kernel 2: out[rows[e]] += vals[e] * weighted_h[cols[e]]
// PDL: blocks may be scheduled during gemm's tail; they preload metadata,
// then the grid-dependency sync gates the gathers/REDs.
// 8 edges per warp, MLP=8. 800000 = 100000*8, no tail.
// ---------------------------------------------------------------------------
__global__ __launch_bounds__(256) void edge_kernel(
    const int* __restrict__ rows,
    const int* __restrict__ cols,
    const float* __restrict__ vals,
    const __half* __restrict__ weighted,
    float* __restrict__ out)
{
    const int warp = (blockIdx.x * blockDim.x + threadIdx.x) >> 5;
    const int lane = threadIdx.x & 31;
    const long long e0 = (long long)warp * E_PER_WARP;

    int   ri = 0, ci = 0;
    float vi = 0.f;
    if (e0 < N_EDGES) {
        const int eidx = (int)e0 + (lane & (E_PER_WARP - 1));
        ri = __ldg(rows + eidx);        // metadata: not written by gemm
        ci = __ldg(cols + eidx);
        vi = __ldg(vals + eidx);
    }

    // wait for gemm's weighted + residual-out writes to be visible
    cudaGridDependencySynchronize();

    if (e0 >= N_EDGES) return;

    uint2 pk[E_PER_WARP];
    #pragma unroll
    for (int i = 0; i < E_PER_WARP; i++) {
        int cc = __shfl_sync(0xffffffffu, ci, i);
        pk[i] = *reinterpret_cast<const uint2*>(weighted + (size_t)cc * D + lane * 4);
    }

    #pragma unroll
    for (int i = 0; i < E_PER_WARP; i++) {
        int   r = __shfl_sync(0xffffffffu, ri, i);
        float v = __shfl_sync(0xffffffffu, vi, i);
        __half2 h0 = *reinterpret_cast<__half2*>(&pk[i].x);
        __half2 h1 = *reinterpret_cast<__half2*>(&pk[i].y);
        float2 f0 = __half22float2(h0);
        float2 f1 = __half22float2(h1);
        float px = v * f0.x, py = v * f0.y, pz = v * f1.x, pw = v * f1.y;
        float* dst = out + (size_t)r * D + lane * 4;
        asm volatile("red.global.add.v4.f32 [%0], {%1,%2,%3,%4};"
                     :: "l"(dst), "f"(px), "f"(py), "f"(pz), "f"(pw)
                     : "memory");
    }
}

// ---------------------------------------------------------------------------
// Launch — pack, then PDL-overlapped gemm, then PDL-overlapped edge.
// ---------------------------------------------------------------------------
extern "C" void kernel_launch(void* const* d_in, const int* in_sizes, int n_in,
                              void* d_out, int out_size)
{
    const float* user_emb = (const float*)d_in[0];
    const float* social_w = (const float*)d_in[1];
    const int*   rows     = (const int*)d_in[2];
    const int*   cols     = (const int*)d_in[3];
    const float* vals     = (const float*)d_in[4];
    float*       out      = (float*)d_out;

    __half* weighted;  cudaGetSymbolAddress((void**)&weighted, g_weighted_h);
    float2* wpack;     cudaGetSymbolAddress((void**)&wpack,    g_wpack);

    // 0. pack W into B-fragment order (overlapped by gemm's A-staging via PDL)
    pack_w_kernel<<<32, 256>>>(social_w, wpack);

    cudaLaunchAttribute pdl[1];
    pdl[0].id = cudaLaunchAttributeProgrammaticStreamSerialization;
    pdl[0].val.programmaticStreamSerializationAllowed = 1;

    // 1. GEMM (tf32 tensor cores) + fused residual init — PDL over pack
    {
        const int smem_bytes = 128 * AS_STRIDE * sizeof(float)
                             + 16 * 16 * 32 * sizeof(float2);   // 67584 + 65536
        cudaFuncSetAttribute(gemm_kernel,
                             cudaFuncAttributeMaxDynamicSharedMemorySize, smem_bytes);
        cudaLaunchConfig_t cfg = {};
        cfg.gridDim = dim3((N_USERS + 127) / 128);              // 391
        cfg.blockDim = dim3(256);
        cfg.dynamicSmemBytes = smem_bytes;
        cfg.stream = 0;
        cfg.attrs = pdl;
        cfg.numAttrs = 1;
        cudaLaunchKernelEx(&cfg, gemm_kernel, user_emb, wpack, weighted, out);
    }

    // 2. scatter-add edges — PDL over gemm
    {
        int nwarps = N_EDGES / E_PER_WARP;              // 100000
        cudaLaunchConfig_t cfg = {};
        cfg.gridDim = dim3((nwarps * 32 + 255) / 256);  // 12500
        cfg.blockDim = dim3(256);
        cfg.dynamicSmemBytes = 0;
        cfg.stream = 0;
        cfg.attrs = pdl;
        cfg.numAttrs = 1;
        cudaLaunchKernelEx(&cfg, edge_kernel, rows, cols, vals,
                           (const __half*)weighted, out);
    }
}